// round 15
// baseline (speedup 1.0000x reference)
#include <cuda_runtime.h>
#include <math.h>
#include <float.h>

// Per-task precomputed gating tables: only 6 distinct taskIDs exist.
__device__ float g_clean[6 * 64];
__device__ float g_std[6 * 64];

// ---------------------------------------------------------------------------
// Kernel 1: per-task precompute (6 blocks x 256 threads). All weights staged
// in shared with ROW STRIDE 33 (conflict-free lane-varying-row GEMM reads).
// ---------------------------------------------------------------------------
__global__ __launch_bounds__(256) void precompute_kernel(
    const float* __restrict__ embed,   // (6, 32)
    const float* __restrict__ ekeys,   // (32, 32)
    const float* __restrict__ Wq,      // (32, 32)
    const float* __restrict__ bq,      // (32)
    const float* __restrict__ Wk,      // (32, 32)
    const float* __restrict__ bk,      // (32)
    const float* __restrict__ Wg,      // (64, 32)
    const float* __restrict__ bg,      // (64)
    const float* __restrict__ Wn,      // (64, 32)
    const float* __restrict__ bn,      // (64)
    float* __restrict__ load_out)      // (64) -> zero it
{
    const int t = blockIdx.x;
    const int tid = threadIdx.x;

    __shared__ float s_wq[32 * 33], s_wk[32 * 33], s_ek[32 * 33];
    __shared__ float s_k[32 * 33];
    __shared__ float s_wg[64 * 33], s_wn[64 * 33];
    __shared__ float s_q[32];
    __shared__ float s_ew[32];

    if (t == 0 && tid < 64) load_out[tid] = 0.0f;

    // Stage matrices padded to stride 33.
    {
        const int row = tid >> 3, col = (tid & 7) * 4;
        {
            const float4 v = ((const float4*)Wq)[tid];
            float* d = s_wq + row * 33 + col;
            d[0] = v.x; d[1] = v.y; d[2] = v.z; d[3] = v.w;
        }
        {
            const float4 v = ((const float4*)Wk)[tid];
            float* d = s_wk + row * 33 + col;
            d[0] = v.x; d[1] = v.y; d[2] = v.z; d[3] = v.w;
        }
        {
            const float4 v = ((const float4*)ekeys)[tid];
            float* d = s_ek + row * 33 + col;
            d[0] = v.x; d[1] = v.y; d[2] = v.z; d[3] = v.w;
        }
        #pragma unroll
        for (int rep = 0; rep < 2; rep++) {
            const int r2 = row + rep * 32;
            {
                const float4 v = ((const float4*)Wg)[tid + rep * 256];
                float* d = s_wg + r2 * 33 + col;
                d[0] = v.x; d[1] = v.y; d[2] = v.z; d[3] = v.w;
            }
            {
                const float4 v = ((const float4*)Wn)[tid + rep * 256];
                float* d = s_wn + r2 * 33 + col;
                d[0] = v.x; d[1] = v.y; d[2] = v.z; d[3] = v.w;
            }
        }
    }
    __syncthreads();

    // q = (embed[t] @ Wq^T + bq) * 1/sqrt(8)
    if (tid < 32) {
        float acc = bq[tid];
        #pragma unroll
        for (int jj = 0; jj < 32; jj++)
            acc = fmaf(embed[t * 32 + jj], s_wq[tid * 33 + jj], acc);
        s_q[tid] = acc * 0.35355339059327373f;
    }

    // k = expert_keys @ Wk^T + bk
    {
        const int p0 = tid * 4;
        #pragma unroll
        for (int q = 0; q < 4; q++) {
            const int p = p0 + q;
            const int s = p >> 5, i = p & 31;
            float acc = bk[i];
            #pragma unroll
            for (int jj = 0; jj < 32; jj++)
                acc = fmaf(s_ek[s * 33 + jj], s_wk[i * 33 + jj], acc);
            s_k[s * 33 + i] = acc;
        }
    }
    __syncthreads();

    // Warp 0 (lanes = experts s): scores, per-head softmax, mean, softmax.
    if (tid < 32) {
        float sc[4];
        #pragma unroll
        for (int h = 0; h < 4; h++) {
            float acc = 0.0f;
            #pragma unroll
            for (int d = 0; d < 8; d++)
                acc = fmaf(s_q[h * 8 + d], s_k[tid * 33 + h * 8 + d], acc);
            sc[h] = acc;
        }
        float aw = 0.0f;
        #pragma unroll
        for (int h = 0; h < 4; h++) {
            float m = sc[h];
            #pragma unroll
            for (int d = 16; d; d >>= 1)
                m = fmaxf(m, __shfl_xor_sync(0xffffffffu, m, d));
            float e = expf(sc[h] - m);
            float sum = e;
            #pragma unroll
            for (int d = 16; d; d >>= 1)
                sum += __shfl_xor_sync(0xffffffffu, sum, d);
            aw += 0.25f * (e / sum);
        }
        float m2 = aw;
        #pragma unroll
        for (int d = 16; d; d >>= 1)
            m2 = fmaxf(m2, __shfl_xor_sync(0xffffffffu, m2, d));
        float e2 = expf(aw - m2);
        float s2 = e2;
        #pragma unroll
        for (int d = 16; d; d >>= 1)
            s2 += __shfl_xor_sync(0xffffffffu, s2, d);
        s_ew[tid] = e2 / s2;
    }
    __syncthreads();

    // clean_logits[e], noise_std[e]; threads 0..63
    if (tid < 64) {
        float c = bg[tid];
        float nv = bn[tid];
        #pragma unroll
        for (int s = 0; s < 32; s++) {
            const float w = s_ew[s];
            c  = fmaf(w, s_wg[tid * 33 + s], c);
            nv = fmaf(w, s_wn[tid * 33 + s], nv);
        }
        g_clean[t * 64 + tid] = c;
        const float sp = (nv > 0.0f) ? (nv + log1pf(expf(-nv)))
                                     : log1pf(expf(nv));
        g_std[t * 64 + tid] = sp + 0.01f;
    }
}

// ---------------------------------------------------------------------------
// Merge two SORTED top-2 pairs where ALL indices of pair A are lower than all
// indices of pair B. Ties then need only '>=' (prefers the lower-index side).
// ---------------------------------------------------------------------------
__device__ __forceinline__ void merge_sorted_lowhi(
    float a0, int ia0, float a1, int ia1,
    float b0, int ib0, float b1, int ib1,
    float& v0, int& i0, float& v1, int& i1)
{
    const bool p = a0 >= b0;
    v0 = fmaxf(a0, b0);
    i0 = p ? ia0 : ib0;
    const float x  = p ? a1 : a0;   // A-side candidate (lower index)
    const int   xi = p ? ia1 : ia0;
    const float y  = p ? b0 : b1;
    const int   yi = p ? ib0 : ib1;
    const bool q = x >= y;
    v1 = fmaxf(x, y);
    i1 = q ? xi : yi;
}

// ---------------------------------------------------------------------------
// Branchless symmetric merge of two sorted top-2 pairs under the total order
// (value desc, index asc). Both sides of a butterfly compute identical output.
// ---------------------------------------------------------------------------
__device__ __forceinline__ void merge2(float& v0, int& i0, float& v1, int& i1,
                                       float ov0, int oi0, float ov1, int oi1)
{
    const bool fw = (v0 > ov0) || (v0 == ov0 && i0 < oi0);
    const float w0  = fw ? v0  : ov0;
    const int   w0i = fw ? i0  : oi0;
    const float c   = fw ? ov0 : v0;
    const int   ci  = fw ? oi0 : i0;
    const float b   = fw ? v1  : ov1;
    const int   bi  = fw ? i1  : oi1;
    const bool  w   = (c > b) || (c == b && ci < bi);
    v0 = w0;  i0 = w0i;
    v1 = w ? c  : b;
    i1 = w ? ci : bi;
}

// ---------------------------------------------------------------------------
// Kernel 2: per-token gating, 8 lanes per token (R11 body, untouched).
// NEW geometry: single-wave grid (1024 blocks < ~1184 concurrent), each block
// runs `iters` iterations over a contiguous token range -> no wave-2 tail.
// ---------------------------------------------------------------------------
__global__ __launch_bounds__(256) void gate_kernel(
    const int*   __restrict__ taskID,
    const float* __restrict__ noise,
    float*       __restrict__ gates,
    float*       __restrict__ loadv,
    int B, int iters)
{
    __shared__ float s_cl[6 * 64];
    __shared__ float s_st[6 * 64];
    __shared__ float s_load[64];

    const int tid = threadIdx.x;
    if (tid < 64) s_load[tid] = 0.0f;
    for (int i = tid; i < 6 * 64; i += 256) {
        s_cl[i] = g_clean[i];
        s_st[i] = g_std[i];
    }
    __syncthreads();

    const int j = tid & 7;              // lane within octet
    const int base0 = j * 4;            // experts of chunk j
    const int base1 = j * 4 + 32;       // experts of chunk j+8
    const float4 z4 = make_float4(0.0f, 0.0f, 0.0f, 0.0f);

    const int tokensPerBlock = iters * 32;
    const int tok0 = blockIdx.x * tokensPerBlock + (tid >> 3);
    const float4* nq = (const float4*)(noise + (size_t)tok0 * 64) + j;
    float4*       gq = (float4*)      (gates + (size_t)tok0 * 64) + j;
    const int*    tp = taskID + tok0;

    auto process = [&](const float4* nqi, float4* gqi, int t, unsigned mask) {
        gqi[0] = z4;
        gqi[8] = z4;
        const float4 n0 = nqi[0];
        const float4 n1 = nqi[8];

        const float4* cl4 = (const float4*)(s_cl + t * 64);
        const float4* st4 = (const float4*)(s_st + t * 64);
        const float4 c0 = cl4[j], c1 = cl4[j + 8];
        const float4 s0 = st4[j], s1 = st4[j + 8];

        const float l0 = fmaf(n0.x, s0.x, c0.x);
        const float l1 = fmaf(n0.y, s0.y, c0.y);
        const float l2 = fmaf(n0.z, s0.z, c0.z);
        const float l3 = fmaf(n0.w, s0.w, c0.w);
        const float l4 = fmaf(n1.x, s1.x, c1.x);
        const float l5 = fmaf(n1.y, s1.y, c1.y);
        const float l6 = fmaf(n1.z, s1.z, c1.z);
        const float l7 = fmaf(n1.w, s1.w, c1.w);

        // ---- local top-2: tournament tree (>= keeps earlier index) ----
        const bool pa = l0 >= l1;
        const float a_hi = fmaxf(l0, l1), a_lo = fminf(l0, l1);
        const int a_hiI = pa ? base0     : base0 + 1;
        const int a_loI = pa ? base0 + 1 : base0;

        const bool pb = l2 >= l3;
        const float b_hi = fmaxf(l2, l3), b_lo = fminf(l2, l3);
        const int b_hiI = pb ? base0 + 2 : base0 + 3;
        const int b_loI = pb ? base0 + 3 : base0 + 2;

        const bool pc = l4 >= l5;
        const float c_hi = fmaxf(l4, l5), c_lo = fminf(l4, l5);
        const int c_hiI = pc ? base1     : base1 + 1;
        const int c_loI = pc ? base1 + 1 : base1;

        const bool pd = l6 >= l7;
        const float d_hi = fmaxf(l6, l7), d_lo = fminf(l6, l7);
        const int d_hiI = pd ? base1 + 2 : base1 + 3;
        const int d_loI = pd ? base1 + 3 : base1 + 2;

        float q0v0, q0v1, q1v0, q1v1;
        int   q0i0, q0i1, q1i0, q1i1;
        merge_sorted_lowhi(a_hi, a_hiI, a_lo, a_loI,
                           b_hi, b_hiI, b_lo, b_loI,
                           q0v0, q0i0, q0v1, q0i1);
        merge_sorted_lowhi(c_hi, c_hiI, c_lo, c_loI,
                           d_hi, d_hiI, d_lo, d_loI,
                           q1v0, q1i0, q1v1, q1i1);

        float v0, v1;
        int i0, i1;
        merge_sorted_lowhi(q0v0, q0i0, q0v1, q0i1,
                           q1v0, q1i0, q1v1, q1i1,
                           v0, i0, v1, i1);

        // ---- 3-step symmetric butterfly within the octet ----
        #pragma unroll
        for (int d = 1; d < 8; d <<= 1) {
            const float ov0 = __shfl_xor_sync(mask, v0, d, 8);
            const int   oi0 = __shfl_xor_sync(mask, i0, d, 8);
            const float ov1 = __shfl_xor_sync(mask, v1, d, 8);
            const int   oi1 = __shfl_xor_sync(mask, i1, d, 8);
            merge2(v0, i0, v1, i1, ov0, oi0, ov1, oi1);
        }

        // softmax over the top-2 (v0 >= v1 -> stable)
        const float e  = __expf(v1 - v0);
        const float ga = __fdividef(1.0f, 1.0f + e);
        const float gb = e * ga;

        // Patch stores: lane ((i>>2)&7)==j owns the quad it zeroed above;
        // same-thread program order => patch lands after the zero.
        float* grow = (float*)(gqi - j);
        if (((i0 >> 2) & 7) == j) grow[i0] = ga;
        if (((i1 >> 2) & 7) == j) grow[i1] = gb;

        if (j == 0) {
            atomicAdd(&s_load[i0], ga);
            atomicAdd(&s_load[i1], gb);
        }
    };

    if ((blockIdx.x + 1) * tokensPerBlock <= B) {
        // Full block: unguarded, pointer-increment loop.
        #pragma unroll 8
        for (int it = 0; it < iters; ++it) {
            const int t = __ldg(tp);
            process(nq, gq, t, 0xffffffffu);
            nq += 512;          // 32 tokens * 16 float4
            gq += 512;
            tp += 32;
        }
    } else {
        // Tail block: guarded (condition uniform within each octet).
        int tok = tok0;
        for (int it = 0; it < iters; ++it) {
            const bool active = tok < B;
            const unsigned mask = __ballot_sync(0xffffffffu, active);
            if (active) {
                process(nq, gq, __ldg(tp), mask);
            }
            nq += 512;
            gq += 512;
            tp += 32;
            tok += 32;
        }
    }

    __syncthreads();
    if (tid < 64) atomicAdd(&loadv[tid], s_load[tid]);
}

// ---------------------------------------------------------------------------
// Launch
// ---------------------------------------------------------------------------
extern "C" void kernel_launch(void* const* d_in, const int* in_sizes, int n_in,
                              void* d_out, int out_size)
{
    const int*   taskID = (const int*)  d_in[0];
    const float* noise  = (const float*)d_in[1];
    const float* embed  = (const float*)d_in[2];
    const float* ekeys  = (const float*)d_in[3];
    const float* Wq     = (const float*)d_in[4];
    const float* bq     = (const float*)d_in[5];
    const float* Wk     = (const float*)d_in[6];
    const float* bk     = (const float*)d_in[7];
    const float* Wg     = (const float*)d_in[8];
    const float* bg     = (const float*)d_in[9];
    const float* Wn     = (const float*)d_in[10];
    const float* bn     = (const float*)d_in[11];

    const int B = in_sizes[0];
    float* gates = (float*)d_out;
    float* loadv = (float*)d_out + (out_size - 64);  // load tail

    precompute_kernel<<<6, 256>>>(embed, ekeys, Wq, bq, Wk, bk,
                                  Wg, bg, Wn, bn, loadv);

    // Single-wave geometry: 1024 blocks (< ~1184 concurrently resident at
    // 8 blocks/SM x 148 SMs), each covering iters*32 contiguous tokens.
    int blocks = 1024;
    const int maxBlocksNeeded = (B + 31) / 32;   // 32 tokens per block-iter
    if (maxBlocksNeeded < blocks) blocks = maxBlocksNeeded;
    const int iters = (B + blocks * 32 - 1) / (blocks * 32);

    gate_kernel<<<blocks, 256>>>(taskID, noise, gates, loadv, B, iters);
}

// round 16
// speedup vs baseline: 1.1101x; 1.1101x over previous
#include <cuda_runtime.h>
#include <math.h>
#include <float.h>

// Per-task precomputed gating tables: only 6 distinct taskIDs exist.
__device__ float g_clean[6 * 64];
__device__ float g_std[6 * 64];

// ---------------------------------------------------------------------------
// Kernel 1: per-task precompute (6 blocks x 256 threads). All weights staged
// in shared with ROW STRIDE 33 (conflict-free lane-varying-row GEMM reads).
// ---------------------------------------------------------------------------
__global__ __launch_bounds__(256) void precompute_kernel(
    const float* __restrict__ embed,   // (6, 32)
    const float* __restrict__ ekeys,   // (32, 32)
    const float* __restrict__ Wq,      // (32, 32)
    const float* __restrict__ bq,      // (32)
    const float* __restrict__ Wk,      // (32, 32)
    const float* __restrict__ bk,      // (32)
    const float* __restrict__ Wg,      // (64, 32)
    const float* __restrict__ bg,      // (64)
    const float* __restrict__ Wn,      // (64, 32)
    const float* __restrict__ bn,      // (64)
    float* __restrict__ load_out)      // (64) -> zero it
{
    const int t = blockIdx.x;
    const int tid = threadIdx.x;

    __shared__ float s_wq[32 * 33], s_wk[32 * 33], s_ek[32 * 33];
    __shared__ float s_k[32 * 33];
    __shared__ float s_wg[64 * 33], s_wn[64 * 33];
    __shared__ float s_q[32];
    __shared__ float s_ew[32];

    if (t == 0 && tid < 64) load_out[tid] = 0.0f;

    // Stage matrices padded to stride 33.
    {
        const int row = tid >> 3, col = (tid & 7) * 4;
        {
            const float4 v = ((const float4*)Wq)[tid];
            float* d = s_wq + row * 33 + col;
            d[0] = v.x; d[1] = v.y; d[2] = v.z; d[3] = v.w;
        }
        {
            const float4 v = ((const float4*)Wk)[tid];
            float* d = s_wk + row * 33 + col;
            d[0] = v.x; d[1] = v.y; d[2] = v.z; d[3] = v.w;
        }
        {
            const float4 v = ((const float4*)ekeys)[tid];
            float* d = s_ek + row * 33 + col;
            d[0] = v.x; d[1] = v.y; d[2] = v.z; d[3] = v.w;
        }
        #pragma unroll
        for (int rep = 0; rep < 2; rep++) {
            const int r2 = row + rep * 32;
            {
                const float4 v = ((const float4*)Wg)[tid + rep * 256];
                float* d = s_wg + r2 * 33 + col;
                d[0] = v.x; d[1] = v.y; d[2] = v.z; d[3] = v.w;
            }
            {
                const float4 v = ((const float4*)Wn)[tid + rep * 256];
                float* d = s_wn + r2 * 33 + col;
                d[0] = v.x; d[1] = v.y; d[2] = v.z; d[3] = v.w;
            }
        }
    }
    __syncthreads();

    // q = (embed[t] @ Wq^T + bq) * 1/sqrt(8)
    if (tid < 32) {
        float acc = bq[tid];
        #pragma unroll
        for (int jj = 0; jj < 32; jj++)
            acc = fmaf(embed[t * 32 + jj], s_wq[tid * 33 + jj], acc);
        s_q[tid] = acc * 0.35355339059327373f;
    }

    // k = expert_keys @ Wk^T + bk
    {
        const int p0 = tid * 4;
        #pragma unroll
        for (int q = 0; q < 4; q++) {
            const int p = p0 + q;
            const int s = p >> 5, i = p & 31;
            float acc = bk[i];
            #pragma unroll
            for (int jj = 0; jj < 32; jj++)
                acc = fmaf(s_ek[s * 33 + jj], s_wk[i * 33 + jj], acc);
            s_k[s * 33 + i] = acc;
        }
    }
    __syncthreads();

    // Warp 0 (lanes = experts s): scores, per-head softmax, mean, softmax.
    if (tid < 32) {
        float sc[4];
        #pragma unroll
        for (int h = 0; h < 4; h++) {
            float acc = 0.0f;
            #pragma unroll
            for (int d = 0; d < 8; d++)
                acc = fmaf(s_q[h * 8 + d], s_k[tid * 33 + h * 8 + d], acc);
            sc[h] = acc;
        }
        float aw = 0.0f;
        #pragma unroll
        for (int h = 0; h < 4; h++) {
            float m = sc[h];
            #pragma unroll
            for (int d = 16; d; d >>= 1)
                m = fmaxf(m, __shfl_xor_sync(0xffffffffu, m, d));
            float e = expf(sc[h] - m);
            float sum = e;
            #pragma unroll
            for (int d = 16; d; d >>= 1)
                sum += __shfl_xor_sync(0xffffffffu, sum, d);
            aw += 0.25f * (e / sum);
        }
        float m2 = aw;
        #pragma unroll
        for (int d = 16; d; d >>= 1)
            m2 = fmaxf(m2, __shfl_xor_sync(0xffffffffu, m2, d));
        float e2 = expf(aw - m2);
        float s2 = e2;
        #pragma unroll
        for (int d = 16; d; d >>= 1)
            s2 += __shfl_xor_sync(0xffffffffu, s2, d);
        s_ew[tid] = e2 / s2;
    }
    __syncthreads();

    // clean_logits[e], noise_std[e]; threads 0..63
    if (tid < 64) {
        float c = bg[tid];
        float nv = bn[tid];
        #pragma unroll
        for (int s = 0; s < 32; s++) {
            const float w = s_ew[s];
            c  = fmaf(w, s_wg[tid * 33 + s], c);
            nv = fmaf(w, s_wn[tid * 33 + s], nv);
        }
        g_clean[t * 64 + tid] = c;
        const float sp = (nv > 0.0f) ? (nv + log1pf(expf(-nv)))
                                     : log1pf(expf(nv));
        g_std[t * 64 + tid] = sp + 0.01f;
    }
}

// ---------------------------------------------------------------------------
// Merge two SORTED top-2 pairs where ALL indices of pair A are lower than all
// indices of pair B. Ties then need only '>=' (prefers the lower-index side).
// ---------------------------------------------------------------------------
__device__ __forceinline__ void merge_sorted_lowhi(
    float a0, int ia0, float a1, int ia1,
    float b0, int ib0, float b1, int ib1,
    float& v0, int& i0, float& v1, int& i1)
{
    const bool p = a0 >= b0;
    v0 = fmaxf(a0, b0);
    i0 = p ? ia0 : ib0;
    const float x  = p ? a1 : a0;   // A-side candidate (lower index)
    const int   xi = p ? ia1 : ia0;
    const float y  = p ? b0 : b1;
    const int   yi = p ? ib0 : ib1;
    const bool q = x >= y;
    v1 = fmaxf(x, y);
    i1 = q ? xi : yi;
}

// ---------------------------------------------------------------------------
// Branchless symmetric merge of two sorted top-2 pairs under the total order
// (value desc, index asc). Both sides of a butterfly compute identical output.
// ---------------------------------------------------------------------------
__device__ __forceinline__ void merge2(float& v0, int& i0, float& v1, int& i1,
                                       float ov0, int oi0, float ov1, int oi1)
{
    const bool fw = (v0 > ov0) || (v0 == ov0 && i0 < oi0);
    const float w0  = fw ? v0  : ov0;
    const int   w0i = fw ? i0  : oi0;
    const float c   = fw ? ov0 : v0;
    const int   ci  = fw ? oi0 : i0;
    const float b   = fw ? v1  : ov1;
    const int   bi  = fw ? i1  : oi1;
    const bool  w   = (c > b) || (c == b && ci < bi);
    v0 = w0;  i0 = w0i;
    v1 = w ? c  : b;
    i1 = w ? ci : bi;
}

// ---------------------------------------------------------------------------
// Kernel 2: per-token gating, 8 lanes per token (R11 body, untouched).
// Geometry via COMPILE-TIME trip count: ITERS iterations per block, grid
// sized so full blocks fit in a single wave (ITERS=16 -> 1024 blocks for
// B=524288). No runtime loop bookkeeping -> register count identical to R11.
// ---------------------------------------------------------------------------
template <int ITERS>
__global__ __launch_bounds__(256) void gate_kernel(
    const int*   __restrict__ taskID,
    const float* __restrict__ noise,
    float*       __restrict__ gates,
    float*       __restrict__ loadv,
    int B)
{
    __shared__ float s_cl[6 * 64];
    __shared__ float s_st[6 * 64];
    __shared__ float s_load[64];

    const int tid = threadIdx.x;
    if (tid < 64) s_load[tid] = 0.0f;
    for (int i = tid; i < 6 * 64; i += 256) {
        s_cl[i] = g_clean[i];
        s_st[i] = g_std[i];
    }
    __syncthreads();

    const int j = tid & 7;              // lane within octet
    const int base0 = j * 4;            // experts of chunk j
    const int base1 = j * 4 + 32;       // experts of chunk j+8
    const float4 z4 = make_float4(0.0f, 0.0f, 0.0f, 0.0f);

    const int tok0 = blockIdx.x * (ITERS * 32) + (tid >> 3);
    const float4* nq = (const float4*)(noise + (size_t)tok0 * 64) + j;
    float4*       gq = (float4*)      (gates + (size_t)tok0 * 64) + j;
    const int*    tp = taskID + tok0;

    auto process = [&](const float4* nqi, float4* gqi, int t, unsigned mask) {
        gqi[0] = z4;
        gqi[8] = z4;
        const float4 n0 = nqi[0];
        const float4 n1 = nqi[8];

        const float4* cl4 = (const float4*)(s_cl + t * 64);
        const float4* st4 = (const float4*)(s_st + t * 64);
        const float4 c0 = cl4[j], c1 = cl4[j + 8];
        const float4 s0 = st4[j], s1 = st4[j + 8];

        const float l0 = fmaf(n0.x, s0.x, c0.x);
        const float l1 = fmaf(n0.y, s0.y, c0.y);
        const float l2 = fmaf(n0.z, s0.z, c0.z);
        const float l3 = fmaf(n0.w, s0.w, c0.w);
        const float l4 = fmaf(n1.x, s1.x, c1.x);
        const float l5 = fmaf(n1.y, s1.y, c1.y);
        const float l6 = fmaf(n1.z, s1.z, c1.z);
        const float l7 = fmaf(n1.w, s1.w, c1.w);

        // ---- local top-2: tournament tree (>= keeps earlier index) ----
        const bool pa = l0 >= l1;
        const float a_hi = fmaxf(l0, l1), a_lo = fminf(l0, l1);
        const int a_hiI = pa ? base0     : base0 + 1;
        const int a_loI = pa ? base0 + 1 : base0;

        const bool pb = l2 >= l3;
        const float b_hi = fmaxf(l2, l3), b_lo = fminf(l2, l3);
        const int b_hiI = pb ? base0 + 2 : base0 + 3;
        const int b_loI = pb ? base0 + 3 : base0 + 2;

        const bool pc = l4 >= l5;
        const float c_hi = fmaxf(l4, l5), c_lo = fminf(l4, l5);
        const int c_hiI = pc ? base1     : base1 + 1;
        const int c_loI = pc ? base1 + 1 : base1;

        const bool pd = l6 >= l7;
        const float d_hi = fmaxf(l6, l7), d_lo = fminf(l6, l7);
        const int d_hiI = pd ? base1 + 2 : base1 + 3;
        const int d_loI = pd ? base1 + 3 : base1 + 2;

        float q0v0, q0v1, q1v0, q1v1;
        int   q0i0, q0i1, q1i0, q1i1;
        merge_sorted_lowhi(a_hi, a_hiI, a_lo, a_loI,
                           b_hi, b_hiI, b_lo, b_loI,
                           q0v0, q0i0, q0v1, q0i1);
        merge_sorted_lowhi(c_hi, c_hiI, c_lo, c_loI,
                           d_hi, d_hiI, d_lo, d_loI,
                           q1v0, q1i0, q1v1, q1i1);

        float v0, v1;
        int i0, i1;
        merge_sorted_lowhi(q0v0, q0i0, q0v1, q0i1,
                           q1v0, q1i0, q1v1, q1i1,
                           v0, i0, v1, i1);

        // ---- 3-step symmetric butterfly within the octet ----
        #pragma unroll
        for (int d = 1; d < 8; d <<= 1) {
            const float ov0 = __shfl_xor_sync(mask, v0, d, 8);
            const int   oi0 = __shfl_xor_sync(mask, i0, d, 8);
            const float ov1 = __shfl_xor_sync(mask, v1, d, 8);
            const int   oi1 = __shfl_xor_sync(mask, i1, d, 8);
            merge2(v0, i0, v1, i1, ov0, oi0, ov1, oi1);
        }

        // softmax over the top-2 (v0 >= v1 -> stable)
        const float e  = __expf(v1 - v0);
        const float ga = __fdividef(1.0f, 1.0f + e);
        const float gb = e * ga;

        // Patch stores: lane ((i>>2)&7)==j owns the quad it zeroed above;
        // same-thread program order => patch lands after the zero.
        float* grow = (float*)(gqi - j);
        if (((i0 >> 2) & 7) == j) grow[i0] = ga;
        if (((i1 >> 2) & 7) == j) grow[i1] = gb;

        if (j == 0) {
            atomicAdd(&s_load[i0], ga);
            atomicAdd(&s_load[i1], gb);
        }
    };

    if ((blockIdx.x + 1) * (ITERS * 32) <= (unsigned)B) {
        // Full block: unguarded, pointer-increment loop (compile-time trip).
        #pragma unroll
        for (int it = 0; it < ITERS; ++it) {
            const int t = __ldg(tp);
            process(nq, gq, t, 0xffffffffu);
            nq += 512;          // 32 tokens * 16 float4
            gq += 512;
            tp += 32;
        }
    } else {
        // Tail block: guarded (condition uniform within each octet).
        int tok = tok0;
        for (int it = 0; it < ITERS; ++it) {
            const bool active = tok < B;
            const unsigned mask = __ballot_sync(0xffffffffu, active);
            if (active) {
                process(nq, gq, __ldg(tp), mask);
            }
            nq += 512;
            gq += 512;
            tp += 32;
            tok += 32;
        }
    }

    __syncthreads();
    if (tid < 64) atomicAdd(&loadv[tid], s_load[tid]);
}

// ---------------------------------------------------------------------------
// Launch
// ---------------------------------------------------------------------------
extern "C" void kernel_launch(void* const* d_in, const int* in_sizes, int n_in,
                              void* d_out, int out_size)
{
    const int*   taskID = (const int*)  d_in[0];
    const float* noise  = (const float*)d_in[1];
    const float* embed  = (const float*)d_in[2];
    const float* ekeys  = (const float*)d_in[3];
    const float* Wq     = (const float*)d_in[4];
    const float* bq     = (const float*)d_in[5];
    const float* Wk     = (const float*)d_in[6];
    const float* bk     = (const float*)d_in[7];
    const float* Wg     = (const float*)d_in[8];
    const float* bg     = (const float*)d_in[9];
    const float* Wn     = (const float*)d_in[10];
    const float* bn     = (const float*)d_in[11];

    const int B = in_sizes[0];
    float* gates = (float*)d_out;
    float* loadv = (float*)d_out + (out_size - 64);  // load tail

    precompute_kernel<<<6, 256>>>(embed, ekeys, Wq, bq, Wk, bk,
                                  Wg, bg, Wn, bn, loadv);

    // Single-wave geometry with compile-time trip count: each block covers
    // 16*32 = 512 tokens. For B=524288 -> exactly 1024 blocks (one wave,
    // all full). General B handled by the guarded tail path.
    const int blocks = (B + 511) / 512;
    gate_kernel<16><<<blocks, 256>>>(taskID, noise, gates, loadv, B);
}